// round 5
// baseline (speedup 1.0000x reference)
#include <cuda_runtime.h>
#include <cuda_bf16.h>
#include <cstdint>

#define BT 16384
#define Dm 1024
#define E  16
#define KN 1024          // k_nodes = BT / E
#define K2 2048          // 2*Dm
#define RES_N (BT * Dm * 2)

// GEMM tiling
#define BM 128
#define BN 128
#define BK 64            // bf16 per k-chunk (128 B rows, SW128)
#define NSTAGE 3
#define NCHUNK 96        // 3 precision passes * (2048 / 64)
#define STAGE_BYTES 32768
#define A_TILE_B 16384

// ---------------- scratch (device globals) ----------------------------------
__device__ float g_scores[BT * E];
__device__ int   g_tidx[KN * E];
__device__ float g_tsc [KN * E];
__device__ float g_counts[BT];
__device__ __nv_bfloat16 g_Ah[(size_t)E * KN * K2];   // [e][kk][k]  hi
__device__ __nv_bfloat16 g_Al[(size_t)E * KN * K2];   //             lo
__device__ __nv_bfloat16 g_Wh[(size_t)E * K2 * K2];   // [e][n_phys][k] hi
__device__ __nv_bfloat16 g_Wl[(size_t)E * K2 * K2];   //               lo

// ---------------- helpers -----------------------------------------------------
__device__ __forceinline__ uint32_t smem_u32(const void* p) {
    uint32_t a;
    asm("{ .reg .u64 t; cvta.to.shared.u64 t, %1; cvt.u32.u64 %0, t; }"
        : "=r"(a) : "l"(p));
    return a;
}
__device__ __forceinline__ uint32_t swz(uint32_t off) {   // SW128
    return off ^ ((off >> 3) & 0x70);
}
__device__ __forceinline__ void ldsm4(uint32_t* r, uint32_t addr) {
    asm volatile("ldmatrix.sync.aligned.m8n8.x4.shared.b16 {%0,%1,%2,%3}, [%4];"
                 : "=r"(r[0]), "=r"(r[1]), "=r"(r[2]), "=r"(r[3]) : "r"(addr));
}
__device__ __forceinline__ void mma16816(float* c, const uint32_t* a,
                                         const uint32_t* b) {
    asm volatile(
        "mma.sync.aligned.m16n8k16.row.col.f32.bf16.bf16.f32 "
        "{%0,%1,%2,%3}, {%4,%5,%6,%7}, {%8,%9}, {%0,%1,%2,%3};"
        : "+f"(c[0]), "+f"(c[1]), "+f"(c[2]), "+f"(c[3])
        : "r"(a[0]), "r"(a[1]), "r"(a[2]), "r"(a[3]), "r"(b[0]), "r"(b[1]));
}
// permute logical column L so each thread's mma fragments hold 4 consecutive n'
__device__ __forceinline__ int permN(int L) {
    int hi = L & ~15, l = L & 15, tg = l >> 2, r = l & 3;
    int q = (r < 2) ? (2 * tg + r) : (8 + 2 * tg + (r - 2));
    return hi | q;
}

// ---------------- 1) gating scores (R3-exact summation order) ----------------
// One thread per (token, expert); single-accumulator sequential-j sum.
// DO NOT change the accumulation order: topk_idx correctness depends on it.
__global__ void gate_kernel(const float* __restrict__ x,
                            const float* __restrict__ gw) {
    int tid = blockIdx.x * blockDim.x + threadIdx.x;
    int e = tid & (E - 1);
    int t = tid >> 4;
    const float* xr = x + (size_t)t * K2;
    float acc = 0.f;
#pragma unroll 8
    for (int j = 0; j < K2; j++)
        acc += xr[j] * gw[j * E + e];
    g_scores[t * E + e] = acc;
    if (e == 0) g_counts[t] = 0.f;
}

// ---------------- 2) per-expert top-k (bitonic, jax ties) + counts -----------
__global__ void topk_kernel() {
    extern __shared__ unsigned long long key[];
    const int e = blockIdx.x;
    const int tid = threadIdx.x;
    const int n = BT;
    for (int i = tid; i < n; i += blockDim.x) {
        float sc = g_scores[i * E + e];
        unsigned u = __float_as_uint(sc);
        u = (u & 0x80000000u) ? ~u : (u | 0x80000000u);
        key[i] = ((unsigned long long)(~u) << 32) | (unsigned)i;
    }
    __syncthreads();
    for (int k = 2; k <= n; k <<= 1) {
        for (int j = k >> 1; j > 0; j >>= 1) {
            for (int i = tid; i < n; i += blockDim.x) {
                int l = i ^ j;
                if (l > i) {
                    unsigned long long a = key[i], b = key[l];
                    bool up = ((i & k) == 0);
                    if (up ? (a > b) : (a < b)) { key[i] = b; key[l] = a; }
                }
            }
            __syncthreads();
        }
    }
    for (int kk = tid; kk < KN; kk += blockDim.x) {
        int idx = (int)(key[kk] & 0xFFFFFFFFull);
        g_tidx[kk * E + e] = idx;
        g_tsc [kk * E + e] = g_scores[idx * E + e];
        atomicAdd(&g_counts[idx], 1.0f);
    }
}

// ---------------- 3) merged build A (gather, hi/lo) + build W ----------------
__global__ void __launch_bounds__(256) build_AW_kernel(const float* __restrict__ x,
                                                       const float* __restrict__ ew) {
    __shared__ float2 tile[32][33];
    int b = blockIdx.x;
    int tid = threadIdx.x;
    if (b < E * KN) {
        int e  = b >> 10;
        int kk = b & (KN - 1);
        int t  = g_tidx[kk * E + e];
        const float2* xr = (const float2*)(x + (size_t)t * K2);
        size_t base = ((size_t)e * KN + kk) * K2;
#pragma unroll
        for (int it = 0; it < Dm / 256; it++) {
            int d = tid + it * 256;
            float2 v = xr[d];
            __nv_bfloat16 hr = __float2bfloat16(v.x);
            __nv_bfloat16 lr = __float2bfloat16(v.x - __bfloat162float(hr));
            __nv_bfloat16 hi = __float2bfloat16(v.y);
            __nv_bfloat16 li = __float2bfloat16(v.y - __bfloat162float(hi));
            g_Ah[base + d]      = hr;
            g_Ah[base + Dm + d] = hi;
            g_Al[base + d]      = lr;
            g_Al[base + Dm + d] = li;
        }
    } else {
        b -= E * KN;
        int e   = b >> 10;
        int rem = b & 1023;
        int d0 = (rem >> 5) * 32;
        int f0 = (rem & 31) * 32;
        int tx = tid & 31, ty = tid >> 5;   // 32 x 8
        const float2* src = (const float2*)ew + ((size_t)e * Dm + d0) * Dm + f0;
#pragma unroll
        for (int i = ty; i < 32; i += 8)
            tile[i][tx] = src[(size_t)i * Dm + tx];
        __syncthreads();
        size_t wb = (size_t)e * K2 * K2;
        int d = d0 + tx;
#pragma unroll
        for (int i = ty; i < 32; i += 8) {
            int f = f0 + i;
            float2 w = tile[tx][i];           // = ew[e][d][f]
            __nv_bfloat16 hr = __float2bfloat16(w.x);
            __nv_bfloat16 lr = __float2bfloat16(w.x - __bfloat162float(hr));
            __nv_bfloat16 hi = __float2bfloat16(w.y);
            __nv_bfloat16 li = __float2bfloat16(w.y - __bfloat162float(hi));
            __nv_bfloat16 hn = __float2bfloat16(-w.y);
            __nv_bfloat16 ln = __float2bfloat16(-w.y - __bfloat162float(hn));
            size_t r0 = wb + (size_t)permN(2 * f)     * K2;   // re output row
            size_t r1 = wb + (size_t)permN(2 * f + 1) * K2;   // im output row
            g_Wh[r0 + d]      = hr;  g_Wl[r0 + d]      = lr;
            g_Wh[r0 + Dm + d] = hn;  g_Wl[r0 + Dm + d] = ln;
            g_Wh[r1 + d]      = hi;  g_Wl[r1 + d]      = li;
            g_Wh[r1 + Dm + d] = hr;  g_Wl[r1 + Dm + d] = lr;
        }
    }
}

// ---------------- 4) mma.sync GEMM + fused vectorized scatter ----------------
__device__ __forceinline__ void load_chunk(int tid, int e, int bm, int bn,
                                           int c, uint32_t sbase) {
    int pass = c >> 5;                 // 0: Ah*Wh  1: Al*Wh  2: Ah*Wl
    int k0 = (c & 31) * BK;
    const __nv_bfloat16* Ab = (pass == 1 ? g_Al : g_Ah) + (size_t)e * KN * K2;
    const __nv_bfloat16* Wb = (pass == 2 ? g_Wl : g_Wh) + (size_t)e * K2 * K2;
#pragma unroll
    for (int j = 0; j < 8; j++) {
        int o = tid + j * 256;
        bool isA = o < 1024;
        int oo = isA ? o : o - 1024;
        int r = oo >> 3;
        int c16 = oo & 7;
        const void* src = isA
            ? (const void*)(Ab + (size_t)(bm + r) * K2 + k0 + c16 * 8)
            : (const void*)(Wb + (size_t)(bn + r) * K2 + k0 + c16 * 8);
        uint32_t dst = sbase + (isA ? 0u : (uint32_t)A_TILE_B)
                     + swz(r * 128 + c16 * 16);
        asm volatile("cp.async.cg.shared.global [%0], [%1], 16;"
                     :: "r"(dst), "l"(src) : "memory");
    }
    asm volatile("cp.async.commit_group;" ::: "memory");
}

__global__ void __launch_bounds__(256, 2) gemm_kernel(float* __restrict__ out) {
    extern __shared__ char smem[];
    const uint32_t SM_TILE = smem_u32(smem);
    const int tid  = threadIdx.x;
    const int wid  = tid >> 5;
    const int lane = tid & 31;
    const int e  = blockIdx.z;
    const int bm = blockIdx.y * BM;
    const int bn = blockIdx.x * BN;

    const int wm = (wid >> 1) * 32;
    const int wn = (wid & 1) * 64;

    float acc[2][8][4];
#pragma unroll
    for (int mt = 0; mt < 2; mt++)
#pragma unroll
        for (int nf = 0; nf < 8; nf++)
#pragma unroll
            for (int r = 0; r < 4; r++) acc[mt][nf][r] = 0.f;

    load_chunk(tid, e, bm, bn, 0, SM_TILE);
    load_chunk(tid, e, bm, bn, 1, SM_TILE + STAGE_BYTES);

    const int lrow = lane & 15;
    const int lkb  = (lane >> 4) * 16;

    for (int i = 0; i < NCHUNK; i++) {
        uint32_t sbase = SM_TILE + (i % NSTAGE) * STAGE_BYTES;
        if (i < NCHUNK - 2)
            asm volatile("cp.async.wait_group 1;" ::: "memory");
        else
            asm volatile("cp.async.wait_group 0;" ::: "memory");
        __syncthreads();

        if (i + 2 < NCHUNK)
            load_chunk(tid, e, bm, bn, i + 2,
                       SM_TILE + ((i + 2) % NSTAGE) * STAGE_BYTES);

#pragma unroll
        for (int ks = 0; ks < 4; ks++) {
            uint32_t a[2][4], bbuf[4][4];
#pragma unroll
            for (int mt = 0; mt < 2; mt++) {
                uint32_t addr = sbase +
                    swz((wm + mt * 16 + lrow) * 128 + ks * 32 + lkb);
                ldsm4(a[mt], addr);
            }
#pragma unroll
            for (int nt = 0; nt < 4; nt++) {
                uint32_t addr = sbase + A_TILE_B +
                    swz((wn + nt * 16 + lrow) * 128 + ks * 32 + lkb);
                ldsm4(bbuf[nt], addr);
            }
#pragma unroll
            for (int mt = 0; mt < 2; mt++)
#pragma unroll
                for (int nt = 0; nt < 4; nt++) {
                    uint32_t b0[2] = { bbuf[nt][0], bbuf[nt][2] };
                    uint32_t b1[2] = { bbuf[nt][1], bbuf[nt][3] };
                    mma16816(acc[mt][nt * 2],     a[mt], b0);
                    mma16816(acc[mt][nt * 2 + 1], a[mt], b1);
                }
        }
    }

    // epilogue: thread owns 4 consecutive output floats per fragment pair
    const int g  = lane >> 2;
    const int tg = lane & 3;
#pragma unroll
    for (int mt = 0; mt < 2; mt++) {
#pragma unroll
        for (int half = 0; half < 2; half++) {
            int kk = bm + wm + mt * 16 + g + half * 8;
            int t = g_tidx[kk * E + e];
            float scale = g_tsc[kk * E + e] / fmaxf(g_counts[t], 1.0f);
            float* obase = out + (size_t)t * K2 + bn + wn + 4 * tg;
#pragma unroll
            for (int j = 0; j < 4; j++) {
                float v0 = acc[mt][2 * j][half * 2 + 0] * scale;
                float v1 = acc[mt][2 * j][half * 2 + 1] * scale;
                float v2 = acc[mt][2 * j + 1][half * 2 + 0] * scale;
                float v3 = acc[mt][2 * j + 1][half * 2 + 1] * scale;
                asm volatile("red.global.add.v4.f32 [%0], {%1,%2,%3,%4};"
                             :: "l"(obase + 16 * j),
                                "f"(v0), "f"(v1), "f"(v2), "f"(v3) : "memory");
            }
        }
    }
}

// ---------------- 5) ModReLU (float4: 2 complex per thread) -------------------
__global__ void finalize_kernel(float* __restrict__ out,
                                const float* __restrict__ bias) {
    size_t i = (size_t)blockIdx.x * blockDim.x + threadIdx.x;  // BT*Dm/2
    int dp = (int)(i & (Dm / 2 - 1));
    float4 z = ((float4*)out)[i];
    float b0 = bias[2 * dp], b1 = bias[2 * dp + 1];
    float m0 = sqrtf(z.x * z.x + z.y * z.y);
    float m1 = sqrtf(z.z * z.z + z.w * z.w);
    float s0 = fmaxf(m0 + b0, 0.f) / fmaxf(m0, 1e-8f);
    float s1 = fmaxf(m1 + b1, 0.f) / fmaxf(m1, 1e-8f);
    z.x *= s0; z.y *= s0; z.z *= s1; z.w *= s1;
    ((float4*)out)[i] = z;
}

// ---------------- 6) optional extras ------------------------------------------
__global__ void extras_kernel(float* __restrict__ out, int avail) {
    int i = blockIdx.x * blockDim.x + threadIdx.x;
    float* ex = out + RES_N;
    if (i < KN * E && i < avail)             ex[i] = (float)g_tidx[i];
    if (i < KN * E && KN * E + i < avail)    ex[KN * E + i] = g_tsc[i];
    if (i < BT    && 2 * KN * E + i < avail) ex[2 * KN * E + i] = g_counts[i];
}

// -------------------------------------------------------------------------------
extern "C" void kernel_launch(void* const* d_in, const int* in_sizes, int n_in,
                              void* d_out, int out_size) {
    const float* x    = (const float*)d_in[0];
    const float* gw   = (const float*)d_in[1];
    const float* ew   = (const float*)d_in[2];
    const float* bias = (const float*)d_in[3];
    float* out = (float*)d_out;

    cudaMemsetAsync(d_out, 0, (size_t)RES_N * sizeof(float), 0);

    gate_kernel<<<(BT * E) / 256, 256>>>(x, gw);

    cudaFuncSetAttribute(topk_kernel,
                         cudaFuncAttributeMaxDynamicSharedMemorySize, 131072);
    topk_kernel<<<E, 1024, 131072>>>();

    build_AW_kernel<<<2 * E * KN, 256>>>(x, ew);

    const int smem_bytes = NSTAGE * STAGE_BYTES;   // 96 KB
    cudaFuncSetAttribute(gemm_kernel,
                         cudaFuncAttributeMaxDynamicSharedMemorySize, smem_bytes);
    gemm_kernel<<<dim3(K2 / BN, KN / BM, E), 256, smem_bytes>>>(out);

    finalize_kernel<<<(BT * Dm / 2) / 256, 256>>>(out, bias);

    if (out_size > RES_N) {
        int avail = out_size - RES_N;
        extras_kernel<<<(BT + 255) / 256, 256>>>(out, avail);
    }
}

// round 6
// speedup vs baseline: 1.3542x; 1.3542x over previous
#include <cuda_runtime.h>
#include <cuda_bf16.h>
#include <cstdint>

#define BT 16384
#define Dm 1024
#define E  16
#define KN 1024          // k_nodes = BT / E
#define K2 2048          // 2*Dm
#define RES_N (BT * Dm * 2)

// GEMM tiling
#define BM 128
#define BN 128
#define BK 64            // bf16 per k-chunk (128 B rows, SW128)
#define NSTAGE 4
#define NCHUNK 96        // 3 precision passes * (2048 / 64)
#define STAGE_BYTES 32768
#define A_TILE_B 16384

// ---------------- scratch (device globals) ----------------------------------
__device__ float g_scores[BT * E];
__device__ int   g_tidx[KN * E];
__device__ float g_tsc [KN * E];
__device__ float g_counts[BT];
__device__ __nv_bfloat16 g_Ah[(size_t)E * KN * K2];   // [e][kk][k]  hi
__device__ __nv_bfloat16 g_Al[(size_t)E * KN * K2];   //             lo
__device__ __nv_bfloat16 g_Wh[(size_t)E * K2 * K2];   // [e][n_phys][k] hi
__device__ __nv_bfloat16 g_Wl[(size_t)E * K2 * K2];   //               lo

// ---------------- helpers -----------------------------------------------------
__device__ __forceinline__ uint32_t smem_u32(const void* p) {
    uint32_t a;
    asm("{ .reg .u64 t; cvta.to.shared.u64 t, %1; cvt.u32.u64 %0, t; }"
        : "=r"(a) : "l"(p));
    return a;
}
__device__ __forceinline__ uint32_t swz(uint32_t off) {   // SW128
    return off ^ ((off >> 3) & 0x70);
}
__device__ __forceinline__ void ldsm4(uint32_t* r, uint32_t addr) {
    asm volatile("ldmatrix.sync.aligned.m8n8.x4.shared.b16 {%0,%1,%2,%3}, [%4];"
                 : "=r"(r[0]), "=r"(r[1]), "=r"(r[2]), "=r"(r[3]) : "r"(addr));
}
__device__ __forceinline__ void mma16816(float* c, const uint32_t* a,
                                         const uint32_t* b) {
    asm volatile(
        "mma.sync.aligned.m16n8k16.row.col.f32.bf16.bf16.f32 "
        "{%0,%1,%2,%3}, {%4,%5,%6,%7}, {%8,%9}, {%0,%1,%2,%3};"
        : "+f"(c[0]), "+f"(c[1]), "+f"(c[2]), "+f"(c[3])
        : "r"(a[0]), "r"(a[1]), "r"(a[2]), "r"(a[3]), "r"(b[0]), "r"(b[1]));
}
// permute logical column L so each thread's mma fragments hold 4 consecutive n'
__device__ __forceinline__ int permN(int L) {
    int hi = L & ~15, l = L & 15, tg = l >> 2, r = l & 3;
    int q = (r < 2) ? (2 * tg + r) : (8 + 2 * tg + (r - 2));
    return hi | q;
}

// ---------------- 1) gating scores (R3-exact summation order) ----------------
// DO NOT change the accumulation order: topk_idx correctness depends on it.
__global__ void gate_kernel(const float* __restrict__ x,
                            const float* __restrict__ gw) {
    int tid = blockIdx.x * blockDim.x + threadIdx.x;
    int e = tid & (E - 1);
    int t = tid >> 4;
    const float* xr = x + (size_t)t * K2;
    float acc = 0.f;
#pragma unroll 8
    for (int j = 0; j < K2; j++)
        acc += xr[j] * gw[j * E + e];
    g_scores[t * E + e] = acc;
    if (e == 0) g_counts[t] = 0.f;
}

// ---------------- 2) per-expert top-k (bitonic, jax ties) + counts -----------
__global__ void topk_kernel() {
    extern __shared__ unsigned long long key[];
    const int e = blockIdx.x;
    const int tid = threadIdx.x;
    const int n = BT;
    for (int i = tid; i < n; i += blockDim.x) {
        float sc = g_scores[i * E + e];
        unsigned u = __float_as_uint(sc);
        u = (u & 0x80000000u) ? ~u : (u | 0x80000000u);
        key[i] = ((unsigned long long)(~u) << 32) | (unsigned)i;
    }
    __syncthreads();
    for (int k = 2; k <= n; k <<= 1) {
        for (int j = k >> 1; j > 0; j >>= 1) {
            for (int i = tid; i < n; i += blockDim.x) {
                int l = i ^ j;
                if (l > i) {
                    unsigned long long a = key[i], b = key[l];
                    bool up = ((i & k) == 0);
                    if (up ? (a > b) : (a < b)) { key[i] = b; key[l] = a; }
                }
            }
            __syncthreads();
        }
    }
    for (int kk = tid; kk < KN; kk += blockDim.x) {
        int idx = (int)(key[kk] & 0xFFFFFFFFull);
        g_tidx[kk * E + e] = idx;
        g_tsc [kk * E + e] = g_scores[idx * E + e];
        atomicAdd(&g_counts[idx], 1.0f);
    }
}

// ---------------- 3) merged build A (gather, hi/lo) + build W ----------------
__global__ void __launch_bounds__(256) build_AW_kernel(const float* __restrict__ x,
                                                       const float* __restrict__ ew) {
    __shared__ float2 tile[32][33];
    int b = blockIdx.x;
    int tid = threadIdx.x;
    if (b < E * KN) {
        int e  = b >> 10;
        int kk = b & (KN - 1);
        int t  = g_tidx[kk * E + e];
        const float2* xr = (const float2*)(x + (size_t)t * K2);
        size_t base = ((size_t)e * KN + kk) * K2;
#pragma unroll
        for (int it = 0; it < Dm / 256; it++) {
            int d = tid + it * 256;
            float2 v = xr[d];
            __nv_bfloat16 hr = __float2bfloat16(v.x);
            __nv_bfloat16 lr = __float2bfloat16(v.x - __bfloat162float(hr));
            __nv_bfloat16 hi = __float2bfloat16(v.y);
            __nv_bfloat16 li = __float2bfloat16(v.y - __bfloat162float(hi));
            g_Ah[base + d]      = hr;
            g_Ah[base + Dm + d] = hi;
            g_Al[base + d]      = lr;
            g_Al[base + Dm + d] = li;
        }
    } else {
        b -= E * KN;
        int e   = b >> 10;
        int rem = b & 1023;
        int d0 = (rem >> 5) * 32;
        int f0 = (rem & 31) * 32;
        int tx = tid & 31, ty = tid >> 5;   // 32 x 8
        const float2* src = (const float2*)ew + ((size_t)e * Dm + d0) * Dm + f0;
#pragma unroll
        for (int i = ty; i < 32; i += 8)
            tile[i][tx] = src[(size_t)i * Dm + tx];
        __syncthreads();
        size_t wb = (size_t)e * K2 * K2;
        int d = d0 + tx;
#pragma unroll
        for (int i = ty; i < 32; i += 8) {
            int f = f0 + i;
            float2 w = tile[tx][i];           // = ew[e][d][f]
            __nv_bfloat16 hr = __float2bfloat16(w.x);
            __nv_bfloat16 lr = __float2bfloat16(w.x - __bfloat162float(hr));
            __nv_bfloat16 hi = __float2bfloat16(w.y);
            __nv_bfloat16 li = __float2bfloat16(w.y - __bfloat162float(hi));
            __nv_bfloat16 hn = __float2bfloat16(-w.y);
            __nv_bfloat16 ln = __float2bfloat16(-w.y - __bfloat162float(hn));
            size_t r0 = wb + (size_t)permN(2 * f)     * K2;   // re output row
            size_t r1 = wb + (size_t)permN(2 * f + 1) * K2;   // im output row
            g_Wh[r0 + d]      = hr;  g_Wl[r0 + d]      = lr;
            g_Wh[r0 + Dm + d] = hn;  g_Wl[r0 + Dm + d] = ln;
            g_Wh[r1 + d]      = hi;  g_Wl[r1 + d]      = li;
            g_Wh[r1 + Dm + d] = hr;  g_Wl[r1 + Dm + d] = lr;
        }
    }
}

// ---------------- 4) mma.sync GEMM + fused vectorized scatter ----------------
__device__ __forceinline__ void load_chunk(int tid, int e, int bm, int bn,
                                           int c, uint32_t sbase) {
    int pass = c >> 5;                 // 0: Ah*Wh  1: Al*Wh  2: Ah*Wl
    int k0 = (c & 31) * BK;
    const __nv_bfloat16* Ab = (pass == 1 ? g_Al : g_Ah) + (size_t)e * KN * K2;
    const __nv_bfloat16* Wb = (pass == 2 ? g_Wl : g_Wh) + (size_t)e * K2 * K2;
#pragma unroll
    for (int j = 0; j < 8; j++) {
        int o = tid + j * 256;
        bool isA = o < 1024;
        int oo = isA ? o : o - 1024;
        int r = oo >> 3;
        int c16 = oo & 7;
        const void* src = isA
            ? (const void*)(Ab + (size_t)(bm + r) * K2 + k0 + c16 * 8)
            : (const void*)(Wb + (size_t)(bn + r) * K2 + k0 + c16 * 8);
        uint32_t dst = sbase + (isA ? 0u : (uint32_t)A_TILE_B)
                     + swz(r * 128 + c16 * 16);
        asm volatile("cp.async.cg.shared.global [%0], [%1], 16;"
                     :: "r"(dst), "l"(src) : "memory");
    }
    asm volatile("cp.async.commit_group;" ::: "memory");
}

__global__ void __launch_bounds__(256) gemm_kernel(float* __restrict__ out) {
    extern __shared__ char smem[];
    const uint32_t SM_TILE = smem_u32(smem);
    const int tid  = threadIdx.x;
    const int wid  = tid >> 5;
    const int lane = tid & 31;
    const int e  = blockIdx.z;
    const int bm = blockIdx.y * BM;
    const int bn = blockIdx.x * BN;

    const int wm = (wid >> 1) * 32;
    const int wn = (wid & 1) * 64;

    float acc[2][8][4];
#pragma unroll
    for (int mt = 0; mt < 2; mt++)
#pragma unroll
        for (int nf = 0; nf < 8; nf++)
#pragma unroll
            for (int r = 0; r < 4; r++) acc[mt][nf][r] = 0.f;

    load_chunk(tid, e, bm, bn, 0, SM_TILE);
    load_chunk(tid, e, bm, bn, 1, SM_TILE + STAGE_BYTES);
    load_chunk(tid, e, bm, bn, 2, SM_TILE + 2 * STAGE_BYTES);

    const int lrow = lane & 15;
    const int lkb  = (lane >> 4) * 16;

    for (int i = 0; i < NCHUNK; i++) {
        uint32_t sbase = SM_TILE + (i % NSTAGE) * STAGE_BYTES;
        if (i + 3 < NCHUNK)
            asm volatile("cp.async.wait_group 2;" ::: "memory");
        else
            asm volatile("cp.async.wait_group 0;" ::: "memory");
        __syncthreads();

        if (i + 3 < NCHUNK)
            load_chunk(tid, e, bm, bn, i + 3,
                       SM_TILE + ((i + 3) % NSTAGE) * STAGE_BYTES);

#pragma unroll
        for (int ks = 0; ks < 4; ks++) {
            uint32_t a[2][4], bbuf[4][4];
#pragma unroll
            for (int mt = 0; mt < 2; mt++) {
                uint32_t addr = sbase +
                    swz((wm + mt * 16 + lrow) * 128 + ks * 32 + lkb);
                ldsm4(a[mt], addr);
            }
#pragma unroll
            for (int nt = 0; nt < 4; nt++) {
                uint32_t addr = sbase + A_TILE_B +
                    swz((wn + nt * 16 + lrow) * 128 + ks * 32 + lkb);
                ldsm4(bbuf[nt], addr);
            }
#pragma unroll
            for (int mt = 0; mt < 2; mt++)
#pragma unroll
                for (int nt = 0; nt < 4; nt++) {
                    uint32_t b0[2] = { bbuf[nt][0], bbuf[nt][2] };
                    uint32_t b1[2] = { bbuf[nt][1], bbuf[nt][3] };
                    mma16816(acc[mt][nt * 2],     a[mt], b0);
                    mma16816(acc[mt][nt * 2 + 1], a[mt], b1);
                }
        }
    }

    // epilogue: thread owns 4 consecutive output floats per fragment pair
    const int g  = lane >> 2;
    const int tg = lane & 3;
#pragma unroll
    for (int mt = 0; mt < 2; mt++) {
#pragma unroll
        for (int half = 0; half < 2; half++) {
            int kk = bm + wm + mt * 16 + g + half * 8;
            int t = g_tidx[kk * E + e];
            float scale = g_tsc[kk * E + e] / fmaxf(g_counts[t], 1.0f);
            float* obase = out + (size_t)t * K2 + bn + wn + 4 * tg;
#pragma unroll
            for (int j = 0; j < 4; j++) {
                float v0 = acc[mt][2 * j][half * 2 + 0] * scale;
                float v1 = acc[mt][2 * j][half * 2 + 1] * scale;
                float v2 = acc[mt][2 * j + 1][half * 2 + 0] * scale;
                float v3 = acc[mt][2 * j + 1][half * 2 + 1] * scale;
                asm volatile("red.global.add.v4.f32 [%0], {%1,%2,%3,%4};"
                             :: "l"(obase + 16 * j),
                                "f"(v0), "f"(v1), "f"(v2), "f"(v3) : "memory");
            }
        }
    }
}

// ---------------- 5) ModReLU (float4: 2 complex per thread) -------------------
__global__ void finalize_kernel(float* __restrict__ out,
                                const float* __restrict__ bias) {
    size_t i = (size_t)blockIdx.x * blockDim.x + threadIdx.x;  // BT*Dm/2
    int dp = (int)(i & (Dm / 2 - 1));
    float4 z = ((float4*)out)[i];
    float b0 = bias[2 * dp], b1 = bias[2 * dp + 1];
    float m0 = sqrtf(z.x * z.x + z.y * z.y);
    float m1 = sqrtf(z.z * z.z + z.w * z.w);
    float s0 = fmaxf(m0 + b0, 0.f) / fmaxf(m0, 1e-8f);
    float s1 = fmaxf(m1 + b1, 0.f) / fmaxf(m1, 1e-8f);
    z.x *= s0; z.y *= s0; z.z *= s1; z.w *= s1;
    ((float4*)out)[i] = z;
}

// ---------------- 6) optional extras ------------------------------------------
__global__ void extras_kernel(float* __restrict__ out, int avail) {
    int i = blockIdx.x * blockDim.x + threadIdx.x;
    float* ex = out + RES_N;
    if (i < KN * E && i < avail)             ex[i] = (float)g_tidx[i];
    if (i < KN * E && KN * E + i < avail)    ex[KN * E + i] = g_tsc[i];
    if (i < BT    && 2 * KN * E + i < avail) ex[2 * KN * E + i] = g_counts[i];
}

// -------------------------------------------------------------------------------
extern "C" void kernel_launch(void* const* d_in, const int* in_sizes, int n_in,
                              void* d_out, int out_size) {
    const float* x    = (const float*)d_in[0];
    const float* gw   = (const float*)d_in[1];
    const float* ew   = (const float*)d_in[2];
    const float* bias = (const float*)d_in[3];
    float* out = (float*)d_out;

    cudaMemsetAsync(d_out, 0, (size_t)RES_N * sizeof(float), 0);   // 1

    gate_kernel<<<(BT * E) / 256, 256>>>(x, gw);                   // 2

    cudaFuncSetAttribute(topk_kernel,
                         cudaFuncAttributeMaxDynamicSharedMemorySize, 131072);
    topk_kernel<<<E, 1024, 131072>>>();                            // 3

    build_AW_kernel<<<2 * E * KN, 256>>>(x, ew);                   // 4

    const int smem_bytes = NSTAGE * STAGE_BYTES;   // 128 KB
    cudaFuncSetAttribute(gemm_kernel,
                         cudaFuncAttributeMaxDynamicSharedMemorySize, smem_bytes);
    gemm_kernel<<<dim3(K2 / BN, KN / BM, E), 256, smem_bytes>>>(out); // 5 (ncu)

    finalize_kernel<<<(BT * Dm / 2) / 256, 256>>>(out, bias);

    if (out_size > RES_N) {
        int avail = out_size - RES_N;
        extras_kernel<<<(BT + 255) / 256, 256>>>(out, avail);
    }
}